// round 10
// baseline (speedup 1.0000x reference)
#include <cuda_runtime.h>
#include <cuda_fp16.h>

// ---------------------------------------------------------------------------
// MLPPredictor: score[e] = W3 @ relu(W2 @ relu(W1 @ [x[src];x[dst]] + b1) + b2) + b3
//
// W1 @ concat(xs,xd) = W1a@xs + W1b@xd -> node-level PQ GEMM (fp32 out),
// then per-edge gather + fused layer2 GEMM + layer3 dot.
//
// R9: persistent edge kernel (148 CTAs), software pipeline: gather of block
// i+1 (LDG slices) overlapped under the MMA mainloop of block i via a
// double-buffered A (H1) smem buffer; cyclic W2 streaming across blocks.
// 8 warps, 64x64 warp tile (min LDS bytes/MMA). fp16 m16n8k16.
// ---------------------------------------------------------------------------

#define D 256
#define NMAX 50000
#define AW 132                  // A frag block (16m x 16k = 128 words) + 4 pad
#define BW 66                   // B frag block (8n  x 16k =  64 words) + 2 pad
#define EA_WORDS (8 * 16 * AW)  // A buffer: 8 Mi x 16 Kk blocks = 16896 words
#define BCH_WORDS (32 * 2 * BW) // B chunk (32 k): 32 Ni x 2 Kk = 4224 words
#define NACH_WORDS (8 * 2 * AW) // node A chunk: 8 Mi x 2 Kk    = 2112 words

static __device__ float g_PQ[(long long)NMAX * 512];
static __device__ int   g_is64;
static __device__ __align__(16) __half g_W1h[256 * 512];
static __device__ __align__(16) __half g_W2h[256 * 256];

__device__ __forceinline__ unsigned f2h2(float lo, float hi) {
    __half2 h = __floats2half2_rn(lo, hi);
    return *reinterpret_cast<unsigned*>(&h);
}

__device__ __forceinline__ void mma16(float* d, const unsigned* a, const unsigned* b) {
    asm volatile(
        "mma.sync.aligned.m16n8k16.row.col.f32.f16.f16.f32 "
        "{%0,%1,%2,%3},{%4,%5,%6,%7},{%8,%9},{%0,%1,%2,%3};\n"
        : "+f"(d[0]), "+f"(d[1]), "+f"(d[2]), "+f"(d[3])
        : "r"(a[0]), "r"(a[1]), "r"(a[2]), "r"(a[3]), "r"(b[0]), "r"(b[1]));
}

// ---------------------------------------------------------------------------
// Weight pre-conversion: fp32 -> fp16 (deterministic, runs every call).
// ---------------------------------------------------------------------------
__global__ void convert_weights(const float* __restrict__ W1, const float* __restrict__ W2) {
    int idx = blockIdx.x * blockDim.x + threadIdx.x;   // one float4 each
    if (idx < 32768) {
        float4 v = ((const float4*)W1)[idx];
        ((__half2*)g_W1h)[idx * 2]     = __floats2half2_rn(v.x, v.y);
        ((__half2*)g_W1h)[idx * 2 + 1] = __floats2half2_rn(v.z, v.w);
    } else if (idx < 49152) {
        int j = idx - 32768;
        float4 v = ((const float4*)W2)[j];
        ((__half2*)g_W2h)[j * 2]     = __floats2half2_rn(v.x, v.y);
        ((__half2*)g_W2h)[j * 2 + 1] = __floats2half2_rn(v.z, v.w);
    }
}

// ---------------------------------------------------------------------------
// Kernel 1: g_PQ[i, n0+c] = sum_k x[i,k] * W1[c, n0+k]
// CTA 128x256, 16 warps, warp tile 64x32 (wm 2 x wn 8), K chunks of 32.
// (unchanged from R7)
// ---------------------------------------------------------------------------
__global__ __launch_bounds__(512) void node_gemm(const float* __restrict__ x,
                                                 int n_nodes) {
    extern __shared__ unsigned sm[];
    unsigned* Af = sm;                      // [2][NACH_WORDS]
    unsigned* Bf = sm + 2 * NACH_WORDS;     // [2][BCH_WORDS]

    const int tid = threadIdx.x, lane = tid & 31, warp = tid >> 5;
    const int wm = warp >> 3, wn = warp & 7;
    const int g = lane >> 2, tg = lane & 3;
    const int m0 = blockIdx.x * 128, n0 = blockIdx.y * 256;

    const int item = tid >> 1, sub = tid & 1;
    const int rA = item & 127, hA = item >> 7;
    const int gA = (rA & 15) & 7, rsA = (rA & 15) >> 3;
    float4 rav[2]; uint4 rwv[2];

    auto LDA = [&](int kt) {
        int gr = m0 + rA; if (gr >= n_nodes) gr = n_nodes - 1;
        const float4* p = (const float4*)(x + (long long)gr * D + kt * 32 + hA * 16 + sub * 8);
        rav[0] = p[0]; rav[1] = p[1];
    };
    auto STA = [&](int buf) {
        unsigned* base = Af + buf * NACH_WORDS + ((rA >> 4) * 2 + hA) * AW + gA * 16 + rsA;
#pragma unroll
        for (int ii = 0; ii < 2; ii++) {
            int i = sub * 2 + ii;
            unsigned* q = base + (i & 1) * 8 + (i >> 1) * 2;
            q[0] = f2h2(rav[ii].x, rav[ii].y);
            q[4] = f2h2(rav[ii].z, rav[ii].w);
        }
    };
    const __half* Brow = g_W1h + (long long)(tid >> 1) * 512 + n0 + (tid & 1) * 16;
    auto LDW = [&](int kt) {
        const uint4* p = (const uint4*)(Brow + kt * 32);
        rwv[0] = p[0]; rwv[1] = p[1];
    };
    auto STW = [&](int buf) {
        const int row = tid >> 1, hB = tid & 1;
        const int Ni = row >> 3, gb = row & 7;
#pragma unroll
        for (int ii = 0; ii < 2; ii++) {
            int i = hB * 2 + ii;
            unsigned* q = Bf + buf * BCH_WORDS + (Ni * 2 + (i >> 1)) * BW + gb * 8 + (i & 1);
            q[0] = rwv[ii].x; q[2] = rwv[ii].y; q[4] = rwv[ii].z; q[6] = rwv[ii].w;
        }
    };

    float acc[4][4][4];
#pragma unroll
    for (int a = 0; a < 4; a++)
#pragma unroll
        for (int b = 0; b < 4; b++)
#pragma unroll
            for (int c = 0; c < 4; c++) acc[a][b][c] = 0.f;

    LDA(0); LDW(0); STA(0); STW(0);
    __syncthreads();

    for (int kt = 0; kt < 8; ++kt) {
        const int cur = kt & 1;
        if (kt < 7) { LDA(kt + 1); LDW(kt + 1); }
        const unsigned* Ac = Af + cur * NACH_WORDS;
        const unsigned* Bc = Bf + cur * BCH_WORDS;
#pragma unroll
        for (int h = 0; h < 2; ++h) {
            uint4 af[4]; uint2 bf[4];
#pragma unroll
            for (int mi = 0; mi < 4; ++mi)
                af[mi] = *(const uint4*)(Ac + ((wm * 4 + mi) * 2 + h) * AW + lane * 4);
#pragma unroll
            for (int ni = 0; ni < 4; ++ni)
                bf[ni] = *(const uint2*)(Bc + ((wn * 4 + ni) * 2 + h) * BW + lane * 2);
#pragma unroll
            for (int mi = 0; mi < 4; ++mi)
#pragma unroll
                for (int ni = 0; ni < 4; ++ni)
                    mma16(acc[mi][ni], (const unsigned*)&af[mi], (const unsigned*)&bf[ni]);
        }
        if (kt < 7) { STA(cur ^ 1); STW(cur ^ 1); }
        __syncthreads();
    }

#pragma unroll
    for (int mi = 0; mi < 4; ++mi) {
        int r0 = m0 + wm * 64 + mi * 16 + g;
        int r1 = r0 + 8;
#pragma unroll
        for (int ni = 0; ni < 4; ++ni) {
            int c = n0 + wn * 32 + ni * 8 + tg * 2;
            if (r0 < n_nodes)
                *(float2*)(g_PQ + (long long)r0 * 512 + c) = make_float2(acc[mi][ni][0], acc[mi][ni][1]);
            if (r1 < n_nodes)
                *(float2*)(g_PQ + (long long)r1 * 512 + c) = make_float2(acc[mi][ni][2], acc[mi][ni][3]);
        }
    }
}

// ---------------------------------------------------------------------------
// Kernel 2: index dtype detection (JAX x64-off downgrades int64 -> int32).
// ---------------------------------------------------------------------------
__global__ void detect_idx64(const int* __restrict__ p, int E) {
    __shared__ int ok;
    if (threadIdx.x == 0) ok = 1;
    __syncthreads();
    int n = E < 1024 ? E : 1024;
    int bad = 0;
    for (int i = threadIdx.x; i < n; i += blockDim.x)
        if (p[2 * i + 1] != 0) bad = 1;
    if (bad) atomicAnd(&ok, 0);
    __syncthreads();
    if (threadIdx.x == 0) g_is64 = ok;
}

// ---------------------------------------------------------------------------
// Kernel 3: PERSISTENT. Each CTA (256 thr, 8 warps, warp 64x64) loops over
// edge blocks of 128; gather of block i+1 is pipelined under the MMA
// mainloop of block i via double-buffered A. W2 streamed cyclically.
// ---------------------------------------------------------------------------
__global__ __launch_bounds__(256) void edge_mlp(const void* __restrict__ srcv,
                                                const void* __restrict__ dstv,
                                                const float* __restrict__ b1,
                                                const float* __restrict__ b2,
                                                const float* __restrict__ W3,
                                                const float* __restrict__ b3,
                                                float* __restrict__ out,
                                                int E, int NB, int grid) {
    extern __shared__ unsigned sm[];
    unsigned* Af0 = sm;                           // [EA_WORDS]
    unsigned* Af1 = sm + EA_WORDS;                // [EA_WORDS]
    unsigned* Bf  = sm + 2 * EA_WORDS;            // [2][BCH_WORDS]
    float* b2s   = (float*)(Bf + 2 * BCH_WORDS);  // 256
    float* w3s   = b2s + 256;                     // 256
    float* b1s   = w3s + 256;                     // 256
    float* score = b1s + 256;                     // 128

    const int tid = threadIdx.x, lane = tid & 31, warp = tid >> 5;
    const int wm = warp >> 2, wn = warp & 3;
    const int g = lane >> 2, tg = lane & 3;
    const int is64 = g_is64;

    // gather mapping: thread -> (row r, column half h)
    const int r = tid >> 1, h = tid & 1;
    const int Mi = r >> 4, gg = (r & 15) & 7, hi = (r & 15) >> 3;
    const unsigned fragbase = (unsigned)(Mi * 16 * AW + gg * 16 + hi);

    b2s[tid] = b2[tid];
    w3s[tid] = W3[tid];
    b1s[tid] = b1[tid];
    const float b3v = b3[0];
    __syncthreads();

    // ---- helpers ----
    const float *PrC, *QrC, *PrN = g_PQ, *QrN = g_PQ;
    auto idxPtr = [&](int blk, const float*& P, const float*& Q) {
        int e = blk * 128 + r;
        if (e >= E) e = 0;
        long long s, d;
        if (is64) { s = ((const long long*)srcv)[e]; d = ((const long long*)dstv)[e]; }
        else      { s = ((const int*)srcv)[e];       d = ((const int*)dstv)[e]; }
        P = g_PQ + s * 512;
        Q = g_PQ + d * 512 + 256;
    };

    float4 pp[4], qq[4];   // one gather slice in flight
    auto load_slice = [&](const float* P, const float* Q, int s) {
        int c4 = (h * 8 + s) * 4;
        const float4* P4 = (const float4*)P + c4;
        const float4* Q4 = (const float4*)Q + c4;
#pragma unroll
        for (int j = 0; j < 4; j++) { pp[j] = P4[j]; qq[j] = Q4[j]; }
    };
    auto store_slice = [&](unsigned* Adst, int s) {
        int Kk = h * 8 + s;
        float v[16];
#pragma unroll
        for (int j = 0; j < 4; j++) {
            float4 bb = *(const float4*)(b1s + Kk * 16 + j * 4);
            v[j * 4 + 0] = fmaxf(pp[j].x + qq[j].x + bb.x, 0.f);
            v[j * 4 + 1] = fmaxf(pp[j].y + qq[j].y + bb.y, 0.f);
            v[j * 4 + 2] = fmaxf(pp[j].z + qq[j].z + bb.z, 0.f);
            v[j * 4 + 3] = fmaxf(pp[j].w + qq[j].w + bb.w, 0.f);
        }
        unsigned* basep = Adst + Kk * AW + fragbase;
#pragma unroll
        for (int t = 0; t < 4; t++) {
            basep[t * 4]     = f2h2(v[2 * t],     v[2 * t + 1]);
            basep[t * 4 + 2] = f2h2(v[8 + 2 * t], v[9 + 2 * t]);
        }
    };

    // B stream: thread = n-row (0..255), 32 halves (4 x uint4) per chunk
    uint4 rwv[4];
    const __half* BrowBase = g_W2h + (long long)tid * 256;
    auto LDW = [&](int ck) {
        const uint4* p = (const uint4*)(BrowBase + ck * 32);
#pragma unroll
        for (int i = 0; i < 4; i++) rwv[i] = p[i];
    };
    const int NiB = tid >> 3, gB = tid & 7;
    auto STW = [&](int buf) {
#pragma unroll
        for (int i = 0; i < 4; i++) {
            unsigned* q = Bf + buf * BCH_WORDS + (NiB * 2 + (i >> 1)) * BW + gB * 8 + (i & 1);
            q[0] = rwv[i].x; q[2] = rwv[i].y; q[4] = rwv[i].z; q[6] = rwv[i].w;
        }
    };

    // ---- prime: full gather of first block into Af0, B chunk 0 into Bf[0] ----
    int b = blockIdx.x;
    idxPtr(b, PrC, QrC);
#pragma unroll
    for (int s = 0; s < 8; s++) { load_slice(PrC, QrC, s); store_slice(Af0, s); }
    LDW(0); STW(0);

    int nb = b + grid;
    bool haveNext = nb < NB;
    if (haveNext) idxPtr(nb, PrN, QrN);
    int curA = 0;
    __syncthreads();

    // ---- persistent block loop ----
    while (true) {
        if (tid < 128) score[tid] = b3v;
        __syncthreads();

        float acc[4][8][4];
#pragma unroll
        for (int a = 0; a < 4; a++)
#pragma unroll
            for (int bb = 0; bb < 8; bb++)
#pragma unroll
                for (int c = 0; c < 4; c++) acc[a][bb][c] = 0.f;

        unsigned* Acur = curA ? Af1 : Af0;
        unsigned* Anxt = curA ? Af0 : Af1;

        for (int kt = 0; kt < 8; ++kt) {
            if (haveNext && kt > 0) store_slice(Anxt, kt - 1);
            if (haveNext) load_slice(PrN, QrN, kt);
            LDW((kt + 1) & 7);   // cyclic: kt==7 prefetches chunk 0 of next block
            const unsigned* Bc = Bf + (kt & 1) * BCH_WORDS;
#pragma unroll
            for (int hh = 0; hh < 2; ++hh) {
                const int Kkg = kt * 2 + hh;
                uint4 af[4]; uint2 bf[8];
#pragma unroll
                for (int mi = 0; mi < 4; ++mi)
                    af[mi] = *(const uint4*)(Acur + ((wm * 4 + mi) * 16 + Kkg) * AW + lane * 4);
#pragma unroll
                for (int ni = 0; ni < 8; ++ni)
                    bf[ni] = *(const uint2*)(Bc + ((wn * 8 + ni) * 2 + hh) * BW + lane * 2);
#pragma unroll
                for (int mi = 0; mi < 4; ++mi)
#pragma unroll
                    for (int ni = 0; ni < 8; ++ni)
                        mma16(acc[mi][ni], (const unsigned*)&af[mi], (const unsigned*)&bf[ni]);
            }
            STW((kt + 1) & 1);
            __syncthreads();
        }
        if (haveNext) store_slice(Anxt, 7);

        // ---- fused layer-2 bias/relu + layer-3 dot reduction ----
#pragma unroll
        for (int mi = 0; mi < 4; ++mi) {
            float rs0 = 0.f, rs1 = 0.f;
#pragma unroll
            for (int ni = 0; ni < 8; ++ni) {
                int n = wn * 64 + ni * 8 + tg * 2;
                float w0 = w3s[n], w1 = w3s[n + 1];
                float c0 = b2s[n], c1 = b2s[n + 1];
                rs0 += fmaxf(acc[mi][ni][0] + c0, 0.f) * w0 + fmaxf(acc[mi][ni][1] + c1, 0.f) * w1;
                rs1 += fmaxf(acc[mi][ni][2] + c0, 0.f) * w0 + fmaxf(acc[mi][ni][3] + c1, 0.f) * w1;
            }
            rs0 += __shfl_xor_sync(0xffffffffu, rs0, 1);
            rs0 += __shfl_xor_sync(0xffffffffu, rs0, 2);
            rs1 += __shfl_xor_sync(0xffffffffu, rs1, 1);
            rs1 += __shfl_xor_sync(0xffffffffu, rs1, 2);
            if (tg == 0) {
                atomicAdd(&score[wm * 64 + mi * 16 + g], rs0);
                atomicAdd(&score[wm * 64 + mi * 16 + g + 8], rs1);
            }
        }
        __syncthreads();

        if (tid < 128) {
            int e = b * 128 + tid;
            if (e < E) out[e] = score[tid];
        }
        __syncthreads();   // out-write done before score re-init next iteration

        if (!haveNext) break;
        b = nb;
        curA ^= 1;
        nb += grid;
        haveNext = nb < NB;
        if (haveNext) idxPtr(nb, PrN, QrN);
    }
}

// ---------------------------------------------------------------------------
// Launch
// ---------------------------------------------------------------------------
extern "C" void kernel_launch(void* const* d_in, const int* in_sizes, int n_in,
                              void* d_out, int out_size) {
    const float* x  = (const float*)d_in[0];
    const void*  sv = d_in[1];
    const void*  dv = d_in[2];
    const float* W1 = (const float*)d_in[3];
    const float* b1 = (const float*)d_in[4];
    const float* W2 = (const float*)d_in[5];
    const float* b2 = (const float*)d_in[6];
    const float* W3 = (const float*)d_in[7];
    const float* b3 = (const float*)d_in[8];
    float* out = (float*)d_out;

    const int n_nodes = in_sizes[0] / D;
    const int E       = in_sizes[1];
    const int NB      = (E + 127) / 128;

    const int SM_NODE = (2 * NACH_WORDS + 2 * BCH_WORDS) * 4;        // 50688 B
    const int SM_EDGE = (2 * EA_WORDS + 2 * BCH_WORDS + 896) * 4;    // 172544 B
    cudaFuncSetAttribute(node_gemm, cudaFuncAttributeMaxDynamicSharedMemorySize, SM_NODE);
    cudaFuncSetAttribute(edge_mlp,  cudaFuncAttributeMaxDynamicSharedMemorySize, SM_EDGE);

    convert_weights<<<192, 256>>>(W1, W2);

    dim3 g1((n_nodes + 127) / 128, 2);
    node_gemm<<<g1, 512, SM_NODE>>>(x, n_nodes);

    detect_idx64<<<1, 256>>>((const int*)sv, E);

    int ge = NB < 148 ? NB : 148;
    edge_mlp<<<ge, 256, SM_EDGE>>>(sv, dv, b1, b2, W3, b3, out, E, NB, ge);
}

// round 11
// speedup vs baseline: 1.1147x; 1.1147x over previous
#include <cuda_runtime.h>
#include <cuda_fp16.h>

// ---------------------------------------------------------------------------
// MLPPredictor: score[e] = W3 @ relu(W2 @ relu(W1 @ [x[src];x[dst]] + b1) + b2) + b3
//
// W1 @ concat(xs,xd) = W1a@xs + W1b@xd -> node-level PQ GEMM (fp32 out),
// then per-edge gather + fused layer2 GEMM + layer3 dot.
//
// R10: edge kernel reshaped for 2 CTAs/SM (256 thr, <=128 regs, 88KB smem):
// warp tile 64x32, two N-passes over a once-gathered A. Cross-CTA overlap
// replaces R9's failed intra-CTA pipelining. fp16 m16n8k16 mma.sync.
// ---------------------------------------------------------------------------

#define D 256
#define NMAX 50000
#define AW 132                  // A frag block (16m x 16k = 128 words) + 4 pad
#define BW 66                   // B frag block (8n  x 16k =  64 words) + 2 pad
#define EA_WORDS (8 * 16 * AW)  // A buffer: 8 Mi x 16 Kk blocks = 16896 words
#define EB_WORDS (16 * 2 * BW)  // edge B chunk (128 n x 32 k) = 2112 words
#define BCH_WORDS (32 * 2 * BW) // node B chunk (256 n x 32 k) = 4224 words
#define NACH_WORDS (8 * 2 * AW) // node A chunk: 8 Mi x 2 Kk   = 2112 words

static __device__ float g_PQ[(long long)NMAX * 512];
static __device__ int   g_is64;
static __device__ __align__(16) __half g_W1h[256 * 512];
static __device__ __align__(16) __half g_W2h[256 * 256];

__device__ __forceinline__ unsigned f2h2(float lo, float hi) {
    __half2 h = __floats2half2_rn(lo, hi);
    return *reinterpret_cast<unsigned*>(&h);
}

__device__ __forceinline__ void mma16(float* d, const unsigned* a, const unsigned* b) {
    asm volatile(
        "mma.sync.aligned.m16n8k16.row.col.f32.f16.f16.f32 "
        "{%0,%1,%2,%3},{%4,%5,%6,%7},{%8,%9},{%0,%1,%2,%3};\n"
        : "+f"(d[0]), "+f"(d[1]), "+f"(d[2]), "+f"(d[3])
        : "r"(a[0]), "r"(a[1]), "r"(a[2]), "r"(a[3]), "r"(b[0]), "r"(b[1]));
}

// ---------------------------------------------------------------------------
// Weight pre-conversion: fp32 -> fp16 (deterministic, runs every call).
// ---------------------------------------------------------------------------
__global__ void convert_weights(const float* __restrict__ W1, const float* __restrict__ W2) {
    int idx = blockIdx.x * blockDim.x + threadIdx.x;   // one float4 each
    if (idx < 32768) {
        float4 v = ((const float4*)W1)[idx];
        ((__half2*)g_W1h)[idx * 2]     = __floats2half2_rn(v.x, v.y);
        ((__half2*)g_W1h)[idx * 2 + 1] = __floats2half2_rn(v.z, v.w);
    } else if (idx < 49152) {
        int j = idx - 32768;
        float4 v = ((const float4*)W2)[j];
        ((__half2*)g_W2h)[j * 2]     = __floats2half2_rn(v.x, v.y);
        ((__half2*)g_W2h)[j * 2 + 1] = __floats2half2_rn(v.z, v.w);
    }
}

// ---------------------------------------------------------------------------
// Kernel 1: g_PQ[i, n0+c] = sum_k x[i,k] * W1[c, n0+k]
// CTA 128x256, 16 warps, warp tile 64x32 (wm 2 x wn 8), K chunks of 32.
// ---------------------------------------------------------------------------
__global__ __launch_bounds__(512) void node_gemm(const float* __restrict__ x,
                                                 int n_nodes) {
    extern __shared__ unsigned sm[];
    unsigned* Af = sm;                      // [2][NACH_WORDS]
    unsigned* Bf = sm + 2 * NACH_WORDS;     // [2][BCH_WORDS]

    const int tid = threadIdx.x, lane = tid & 31, warp = tid >> 5;
    const int wm = warp >> 3, wn = warp & 7;
    const int g = lane >> 2, tg = lane & 3;
    const int m0 = blockIdx.x * 128, n0 = blockIdx.y * 256;

    const int item = tid >> 1, sub = tid & 1;
    const int rA = item & 127, hA = item >> 7;
    const int gA = (rA & 15) & 7, rsA = (rA & 15) >> 3;
    float4 rav[2]; uint4 rwv[2];

    auto LDA = [&](int kt) {
        int gr = m0 + rA; if (gr >= n_nodes) gr = n_nodes - 1;
        const float4* p = (const float4*)(x + (long long)gr * D + kt * 32 + hA * 16 + sub * 8);
        rav[0] = p[0]; rav[1] = p[1];
    };
    auto STA = [&](int buf) {
        unsigned* base = Af + buf * NACH_WORDS + ((rA >> 4) * 2 + hA) * AW + gA * 16 + rsA;
#pragma unroll
        for (int ii = 0; ii < 2; ii++) {
            int i = sub * 2 + ii;
            unsigned* q = base + (i & 1) * 8 + (i >> 1) * 2;
            q[0] = f2h2(rav[ii].x, rav[ii].y);
            q[4] = f2h2(rav[ii].z, rav[ii].w);
        }
    };
    const __half* Brow = g_W1h + (long long)(tid >> 1) * 512 + n0 + (tid & 1) * 16;
    auto LDW = [&](int kt) {
        const uint4* p = (const uint4*)(Brow + kt * 32);
        rwv[0] = p[0]; rwv[1] = p[1];
    };
    auto STW = [&](int buf) {
        const int row = tid >> 1, hB = tid & 1;
        const int Ni = row >> 3, gb = row & 7;
#pragma unroll
        for (int ii = 0; ii < 2; ii++) {
            int i = hB * 2 + ii;
            unsigned* q = Bf + buf * BCH_WORDS + (Ni * 2 + (i >> 1)) * BW + gb * 8 + (i & 1);
            q[0] = rwv[ii].x; q[2] = rwv[ii].y; q[4] = rwv[ii].z; q[6] = rwv[ii].w;
        }
    };

    float acc[4][4][4];
#pragma unroll
    for (int a = 0; a < 4; a++)
#pragma unroll
        for (int b = 0; b < 4; b++)
#pragma unroll
            for (int c = 0; c < 4; c++) acc[a][b][c] = 0.f;

    LDA(0); LDW(0); STA(0); STW(0);
    __syncthreads();

    for (int kt = 0; kt < 8; ++kt) {
        const int cur = kt & 1;
        if (kt < 7) { LDA(kt + 1); LDW(kt + 1); }
        const unsigned* Ac = Af + cur * NACH_WORDS;
        const unsigned* Bc = Bf + cur * BCH_WORDS;
#pragma unroll
        for (int h = 0; h < 2; ++h) {
            uint4 af[4]; uint2 bf[4];
#pragma unroll
            for (int mi = 0; mi < 4; ++mi)
                af[mi] = *(const uint4*)(Ac + ((wm * 4 + mi) * 2 + h) * AW + lane * 4);
#pragma unroll
            for (int ni = 0; ni < 4; ++ni)
                bf[ni] = *(const uint2*)(Bc + ((wn * 4 + ni) * 2 + h) * BW + lane * 2);
#pragma unroll
            for (int mi = 0; mi < 4; ++mi)
#pragma unroll
                for (int ni = 0; ni < 4; ++ni)
                    mma16(acc[mi][ni], (const unsigned*)&af[mi], (const unsigned*)&bf[ni]);
        }
        if (kt < 7) { STA(cur ^ 1); STW(cur ^ 1); }
        __syncthreads();
    }

#pragma unroll
    for (int mi = 0; mi < 4; ++mi) {
        int r0 = m0 + wm * 64 + mi * 16 + g;
        int r1 = r0 + 8;
#pragma unroll
        for (int ni = 0; ni < 4; ++ni) {
            int c = n0 + wn * 32 + ni * 8 + tg * 2;
            if (r0 < n_nodes)
                *(float2*)(g_PQ + (long long)r0 * 512 + c) = make_float2(acc[mi][ni][0], acc[mi][ni][1]);
            if (r1 < n_nodes)
                *(float2*)(g_PQ + (long long)r1 * 512 + c) = make_float2(acc[mi][ni][2], acc[mi][ni][3]);
        }
    }
}

// ---------------------------------------------------------------------------
// Kernel 2: index dtype detection (JAX x64-off downgrades int64 -> int32).
// ---------------------------------------------------------------------------
__global__ void detect_idx64(const int* __restrict__ p, int E) {
    __shared__ int ok;
    if (threadIdx.x == 0) ok = 1;
    __syncthreads();
    int n = E < 1024 ? E : 1024;
    int bad = 0;
    for (int i = threadIdx.x; i < n; i += blockDim.x)
        if (p[2 * i + 1] != 0) bad = 1;
    if (bad) atomicAnd(&ok, 0);
    __syncthreads();
    if (threadIdx.x == 0) g_is64 = ok;
}

// ---------------------------------------------------------------------------
// Kernel 3: 128 edges/CTA, 256 threads, 2 CTAs/SM. Gather H1 once into
// fragment layout; two N-passes of warp-64x32 MMA; fused relu(+b2)*w3 + b3.
// ---------------------------------------------------------------------------
__global__ __launch_bounds__(256, 2) void edge_mlp(const void* __restrict__ srcv,
                                                   const void* __restrict__ dstv,
                                                   const float* __restrict__ b1,
                                                   const float* __restrict__ b2,
                                                   const float* __restrict__ W3,
                                                   const float* __restrict__ b3,
                                                   float* __restrict__ out, int E) {
    extern __shared__ unsigned sm[];
    unsigned* Af = sm;                        // [EA_WORDS]
    unsigned* Bf = sm + EA_WORDS;             // [2][EB_WORDS]
    float* b2s   = (float*)(Bf + 2 * EB_WORDS);   // 256
    float* w3s   = b2s + 256;                     // 256
    float* b1s   = w3s + 256;                     // 256
    float* score = b1s + 256;                     // 128

    const int tid = threadIdx.x, lane = tid & 31, warp = tid >> 5;
    const int wm = warp >> 2, wn = warp & 3;
    const int g = lane >> 2, tg = lane & 3;
    const int e0 = blockIdx.x * 128;
    const int is64 = g_is64;

    b2s[tid] = b2[tid];
    w3s[tid] = W3[tid];
    b1s[tid] = b1[tid];
    if (tid < 128) score[tid] = b3[0];
    __syncthreads();

    // B chunk stream: 128 rows x 32 halves, thread -> (row=tid>>1, hB=tid&1)
    uint4 rwv[2];
    const int rowB = tid >> 1, hB = tid & 1;
    const int NiB = rowB >> 3, gB = rowB & 7;
    auto LDW = [&](const __half* Brow, int kt) {
        const uint4* p = (const uint4*)(Brow + kt * 32);
        rwv[0] = p[0]; rwv[1] = p[1];
    };
    auto STW = [&](int buf) {
#pragma unroll
        for (int ii = 0; ii < 2; ii++) {
            int i = hB * 2 + ii;
            unsigned* q = Bf + buf * EB_WORDS + (NiB * 2 + (i >> 1)) * BW + gB * 8 + (i & 1);
            q[0] = rwv[ii].x; q[2] = rwv[ii].y; q[4] = rwv[ii].z; q[6] = rwv[ii].w;
        }
    };

    const __half* Brow0 = g_W2h + (long long)rowB * 256 + hB * 16;   // pass 0 rows
    LDW(Brow0, 0);   // overlap W2 chunk-0 with the gather

    // ---- gather + layer 1: row r = tid>>1, column half h = tid&1 ----
    {
        const int r = tid >> 1, h = tid & 1;
        const int Mi = r >> 4, gg = (r & 15) & 7, hi = (r & 15) >> 3;
        unsigned* fragp = Af + Mi * 16 * AW + gg * 16 + hi;
        int e = e0 + r;
        if (e >= E) e = 0;   // garbage rows computed, never stored
        long long s, d;
        if (is64) { s = ((const long long*)srcv)[e]; d = ((const long long*)dstv)[e]; }
        else      { s = ((const int*)srcv)[e];       d = ((const int*)dstv)[e]; }
        const float4* P4 = (const float4*)(g_PQ + s * 512) + h * 32;
        const float4* Q4 = (const float4*)(g_PQ + d * 512 + 256) + h * 32;
        const float4* B4 = (const float4*)b1s + h * 32;
#pragma unroll
        for (int ss = 0; ss < 8; ss++) {
            float v[16];
#pragma unroll
            for (int j = 0; j < 4; j++) {
                float4 p = P4[ss * 4 + j];
                float4 q = Q4[ss * 4 + j];
                float4 bb = B4[ss * 4 + j];
                v[j * 4 + 0] = fmaxf(p.x + q.x + bb.x, 0.f);
                v[j * 4 + 1] = fmaxf(p.y + q.y + bb.y, 0.f);
                v[j * 4 + 2] = fmaxf(p.z + q.z + bb.z, 0.f);
                v[j * 4 + 3] = fmaxf(p.w + q.w + bb.w, 0.f);
            }
            unsigned* basep = fragp + (h * 8 + ss) * AW;
#pragma unroll
            for (int t = 0; t < 4; t++) {
                basep[t * 4]     = f2h2(v[2 * t],     v[2 * t + 1]);
                basep[t * 4 + 2] = f2h2(v[8 + 2 * t], v[9 + 2 * t]);
            }
        }
    }
    STW(0);
    __syncthreads();

    // ---- two N-passes ----
#pragma unroll 1
    for (int nc = 0; nc < 2; ++nc) {
        const __half* Brow = g_W2h + (long long)(nc * 128 + rowB) * 256 + hB * 16;

        float acc[4][4][4];
#pragma unroll
        for (int a = 0; a < 4; a++)
#pragma unroll
            for (int b = 0; b < 4; b++)
#pragma unroll
                for (int c = 0; c < 4; c++) acc[a][b][c] = 0.f;

        if (nc == 1) { LDW(Brow, 0); STW(0); __syncthreads(); }

        for (int kt = 0; kt < 8; ++kt) {
            const int cur = kt & 1;
            if (kt < 7) LDW(Brow, kt + 1);
            const unsigned* Bc = Bf + cur * EB_WORDS;
#pragma unroll
            for (int h = 0; h < 2; ++h) {
                const int Kkg = kt * 2 + h;
                uint4 af[4]; uint2 bf[4];
#pragma unroll
                for (int mi = 0; mi < 4; ++mi)
                    af[mi] = *(const uint4*)(Af + ((wm * 4 + mi) * 16 + Kkg) * AW + lane * 4);
#pragma unroll
                for (int ni = 0; ni < 4; ++ni)
                    bf[ni] = *(const uint2*)(Bc + ((wn * 4 + ni) * 2 + h) * BW + lane * 2);
#pragma unroll
                for (int mi = 0; mi < 4; ++mi)
#pragma unroll
                    for (int ni = 0; ni < 4; ++ni)
                        mma16(acc[mi][ni], (const unsigned*)&af[mi], (const unsigned*)&bf[ni]);
            }
            if (kt < 7) STW(cur ^ 1);
            __syncthreads();
        }

        // ---- fused layer-2 bias/relu + layer-3 dot reduction ----
#pragma unroll
        for (int mi = 0; mi < 4; ++mi) {
            float rs0 = 0.f, rs1 = 0.f;
#pragma unroll
            for (int ni = 0; ni < 4; ++ni) {
                int n = nc * 128 + wn * 32 + ni * 8 + tg * 2;
                float w0 = w3s[n], w1 = w3s[n + 1];
                float c0 = b2s[n], c1 = b2s[n + 1];
                rs0 += fmaxf(acc[mi][ni][0] + c0, 0.f) * w0 + fmaxf(acc[mi][ni][1] + c1, 0.f) * w1;
                rs1 += fmaxf(acc[mi][ni][2] + c0, 0.f) * w0 + fmaxf(acc[mi][ni][3] + c1, 0.f) * w1;
            }
            rs0 += __shfl_xor_sync(0xffffffffu, rs0, 1);
            rs0 += __shfl_xor_sync(0xffffffffu, rs0, 2);
            rs1 += __shfl_xor_sync(0xffffffffu, rs1, 1);
            rs1 += __shfl_xor_sync(0xffffffffu, rs1, 2);
            if (tg == 0) {
                atomicAdd(&score[wm * 64 + mi * 16 + g], rs0);
                atomicAdd(&score[wm * 64 + mi * 16 + g + 8], rs1);
            }
        }
        __syncthreads();
    }

    if (tid < 128) {
        int e = e0 + tid;
        if (e < E) out[e] = score[tid];
    }
}

// ---------------------------------------------------------------------------
// Launch
// ---------------------------------------------------------------------------
extern "C" void kernel_launch(void* const* d_in, const int* in_sizes, int n_in,
                              void* d_out, int out_size) {
    const float* x  = (const float*)d_in[0];
    const void*  sv = d_in[1];
    const void*  dv = d_in[2];
    const float* W1 = (const float*)d_in[3];
    const float* b1 = (const float*)d_in[4];
    const float* W2 = (const float*)d_in[5];
    const float* b2 = (const float*)d_in[6];
    const float* W3 = (const float*)d_in[7];
    const float* b3 = (const float*)d_in[8];
    float* out = (float*)d_out;

    const int n_nodes = in_sizes[0] / D;
    const int E       = in_sizes[1];

    const int SM_NODE = (2 * NACH_WORDS + 2 * BCH_WORDS) * 4;     // 50688 B
    const int SM_EDGE = (EA_WORDS + 2 * EB_WORDS + 896) * 4;      // 88064 B
    cudaFuncSetAttribute(node_gemm, cudaFuncAttributeMaxDynamicSharedMemorySize, SM_NODE);
    cudaFuncSetAttribute(edge_mlp,  cudaFuncAttributeMaxDynamicSharedMemorySize, SM_EDGE);

    convert_weights<<<192, 256>>>(W1, W2);

    dim3 g1((n_nodes + 127) / 128, 2);
    node_gemm<<<g1, 512, SM_NODE>>>(x, n_nodes);

    detect_idx64<<<1, 256>>>((const int*)sv, E);

    int g2 = (E + 127) / 128;
    edge_mlp<<<g2, 256, SM_EDGE>>>(sv, dv, b1, b2, W3, b3, out, E);
}

// round 12
// speedup vs baseline: 1.5890x; 1.4255x over previous
#include <cuda_runtime.h>
#include <cuda_fp16.h>

// ---------------------------------------------------------------------------
// MLPPredictor: score[e] = W3 @ relu(W2 @ relu(W1 @ [x[src];x[dst]] + b1) + b2) + b3
//
// W1 @ concat(xs,xd) = W1a@xs + W1b@xd -> node-level PQ GEMM, then per-edge
// gather + fused layer2 GEMM + layer3 dot.
//
// R11 = R7 (best: 512 thr, 16 warps, warp 64x32, fp16 m16n8k16) +
//   - g_PQ stored fp16 (halves gather traffic; L2-resident)
//   - XOR bank-swizzle on A-fragment smem layout (STS conflicts 4-8x -> ~2x)
//   - fully-coalesced uint4 gather
//   - merged prep kernel
// ---------------------------------------------------------------------------

#define D 256
#define NMAX 50000
#define AW 132                  // A frag block (16m x 16k = 128 words) + 4 pad
#define BW 66                   // B frag block (8n  x 16k =  64 words) + 2 pad
#define EA_WORDS (8 * 16 * AW)  // edge A: 8 Mi x 16 Kk blocks = 16896 words
#define BCH_WORDS (32 * 2 * BW) // B chunk (32 k): 32 Ni x 2 Kk = 4224 words
#define NACH_WORDS (8 * 2 * AW) // node A chunk: 8 Mi x 2 Kk    = 2112 words

static __device__ __align__(16) __half g_PQh[(long long)NMAX * 512];  // 51.2 MB
static __device__ int   g_is64;
static __device__ __align__(16) __half g_W1h[256 * 512];
static __device__ __align__(16) __half g_W2h[256 * 256];

__device__ __forceinline__ unsigned f2h2(float lo, float hi) {
    __half2 h = __floats2half2_rn(lo, hi);
    return *reinterpret_cast<unsigned*>(&h);
}
__device__ __forceinline__ float2 h2f(unsigned u) {
    return __half22float2(*reinterpret_cast<__half2*>(&u));
}

__device__ __forceinline__ void mma16(float* d, const unsigned* a, const unsigned* b) {
    asm volatile(
        "mma.sync.aligned.m16n8k16.row.col.f32.f16.f16.f32 "
        "{%0,%1,%2,%3},{%4,%5,%6,%7},{%8,%9},{%0,%1,%2,%3};\n"
        : "+f"(d[0]), "+f"(d[1]), "+f"(d[2]), "+f"(d[3])
        : "r"(a[0]), "r"(a[1]), "r"(a[2]), "r"(a[3]), "r"(b[0]), "r"(b[1]));
}

// A-fragment reader: swizzled LDS.128 address (conflict-free; matches writers)
__device__ __forceinline__ unsigned a_rd_off(int lane) {
    return (unsigned)((lane * 4) ^ (((lane >> 3) & 3) << 2));
}

// ---------------------------------------------------------------------------
// prep: weight fp32->fp16 conversion (blocks 0..191) + idx dtype detect (192).
// ---------------------------------------------------------------------------
__global__ void prep(const float* __restrict__ W1, const float* __restrict__ W2,
                     const int* __restrict__ p, int E) {
    if (blockIdx.x < 192) {
        int idx = blockIdx.x * blockDim.x + threadIdx.x;
        if (idx < 32768) {
            float4 v = ((const float4*)W1)[idx];
            ((__half2*)g_W1h)[idx * 2]     = __floats2half2_rn(v.x, v.y);
            ((__half2*)g_W1h)[idx * 2 + 1] = __floats2half2_rn(v.z, v.w);
        } else if (idx < 49152) {
            int j = idx - 32768;
            float4 v = ((const float4*)W2)[j];
            ((__half2*)g_W2h)[j * 2]     = __floats2half2_rn(v.x, v.y);
            ((__half2*)g_W2h)[j * 2 + 1] = __floats2half2_rn(v.z, v.w);
        }
    } else {
        __shared__ int ok;
        if (threadIdx.x == 0) ok = 1;
        __syncthreads();
        int n = E < 1024 ? E : 1024;
        int bad = 0;
        for (int i = threadIdx.x; i < n; i += blockDim.x)
            if (p[2 * i + 1] != 0) bad = 1;
        if (bad) atomicAnd(&ok, 0);
        __syncthreads();
        if (threadIdx.x == 0) g_is64 = ok;
    }
}

// ---------------------------------------------------------------------------
// Kernel 1: g_PQh[i, n0+c] = fp16( sum_k x[i,k] * W1[c, n0+k] )
// CTA 128x256, 16 warps, warp tile 64x32, K chunks of 32, double-buffered.
// ---------------------------------------------------------------------------
__global__ __launch_bounds__(512) void node_gemm(const float* __restrict__ x,
                                                 int n_nodes) {
    extern __shared__ unsigned sm[];
    unsigned* Af = sm;                      // [2][NACH_WORDS]
    unsigned* Bf = sm + 2 * NACH_WORDS;     // [2][BCH_WORDS]

    const int tid = threadIdx.x, lane = tid & 31, warp = tid >> 5;
    const int wm = warp >> 3, wn = warp & 7;
    const int g = lane >> 2, tg = lane & 3;
    const int m0 = blockIdx.x * 128, n0 = blockIdx.y * 256;

    const int item = tid >> 1, sub = tid & 1;
    const int rA = item & 127, hA = item >> 7;
    const int gA = (rA & 15) & 7, rsA = (rA & 15) >> 3;
    const int swA = (gA >> 1) & 3;
    float4 rav[2]; uint4 rwv[2];

    auto LDA = [&](int kt) {
        int gr = m0 + rA; if (gr >= n_nodes) gr = n_nodes - 1;
        const float4* p = (const float4*)(x + (long long)gr * D + kt * 32 + hA * 16 + sub * 8);
        rav[0] = p[0]; rav[1] = p[1];
    };
    auto STA = [&](int buf) {
        unsigned* base = Af + buf * NACH_WORDS + ((rA >> 4) * 2 + hA) * AW + gA * 16 + rsA;
#pragma unroll
        for (int ii = 0; ii < 2; ii++) {
            int i = sub * 2 + ii;
            int t0 = (2 * i) & 3, t1 = (2 * i + 1) & 3, ch = i >> 1;
            base[((t0 ^ swA) << 2) + ch * 2] = f2h2(rav[ii].x, rav[ii].y);
            base[((t1 ^ swA) << 2) + ch * 2] = f2h2(rav[ii].z, rav[ii].w);
        }
    };
    const __half* Brow = g_W1h + (long long)(tid >> 1) * 512 + n0 + (tid & 1) * 16;
    auto LDW = [&](int kt) {
        const uint4* p = (const uint4*)(Brow + kt * 32);
        rwv[0] = p[0]; rwv[1] = p[1];
    };
    auto STW = [&](int buf) {
        const int row = tid >> 1, hB = tid & 1;
        const int Ni = row >> 3, gb = row & 7;
#pragma unroll
        for (int ii = 0; ii < 2; ii++) {
            int i = hB * 2 + ii;
            unsigned* q = Bf + buf * BCH_WORDS + (Ni * 2 + (i >> 1)) * BW + gb * 8 + (i & 1);
            q[0] = rwv[ii].x; q[2] = rwv[ii].y; q[4] = rwv[ii].z; q[6] = rwv[ii].w;
        }
    };

    float acc[4][4][4];
#pragma unroll
    for (int a = 0; a < 4; a++)
#pragma unroll
        for (int b = 0; b < 4; b++)
#pragma unroll
            for (int c = 0; c < 4; c++) acc[a][b][c] = 0.f;

    LDA(0); LDW(0); STA(0); STW(0);
    __syncthreads();

    const unsigned aoff = a_rd_off(lane);
    for (int kt = 0; kt < 8; ++kt) {
        const int cur = kt & 1;
        if (kt < 7) { LDA(kt + 1); LDW(kt + 1); }
        const unsigned* Ac = Af + cur * NACH_WORDS;
        const unsigned* Bc = Bf + cur * BCH_WORDS;
#pragma unroll
        for (int h = 0; h < 2; ++h) {
            uint4 af[4]; uint2 bf[4];
#pragma unroll
            for (int mi = 0; mi < 4; ++mi)
                af[mi] = *(const uint4*)(Ac + ((wm * 4 + mi) * 2 + h) * AW + aoff);
#pragma unroll
            for (int ni = 0; ni < 4; ++ni)
                bf[ni] = *(const uint2*)(Bc + ((wn * 4 + ni) * 2 + h) * BW + lane * 2);
#pragma unroll
            for (int mi = 0; mi < 4; ++mi)
#pragma unroll
                for (int ni = 0; ni < 4; ++ni)
                    mma16(acc[mi][ni], (const unsigned*)&af[mi], (const unsigned*)&bf[ni]);
        }
        if (kt < 7) { STA(cur ^ 1); STW(cur ^ 1); }
        __syncthreads();
    }

#pragma unroll
    for (int mi = 0; mi < 4; ++mi) {
        int r0 = m0 + wm * 64 + mi * 16 + g;
        int r1 = r0 + 8;
#pragma unroll
        for (int ni = 0; ni < 4; ++ni) {
            int c = n0 + wn * 32 + ni * 8 + tg * 2;
            if (r0 < n_nodes)
                *(unsigned*)(g_PQh + (long long)r0 * 512 + c) = f2h2(acc[mi][ni][0], acc[mi][ni][1]);
            if (r1 < n_nodes)
                *(unsigned*)(g_PQh + (long long)r1 * 512 + c) = f2h2(acc[mi][ni][2], acc[mi][ni][3]);
        }
    }
}

// ---------------------------------------------------------------------------
// Kernel 3: 128 edges/CTA, 512 threads, 16 warps, warp 64x32, one N pass.
// Gather H1 = relu(P[src]+Q[dst]+b1) from fp16 PQ into swizzled fragment smem.
// ---------------------------------------------------------------------------
__global__ __launch_bounds__(512) void edge_mlp(const void* __restrict__ srcv,
                                                const void* __restrict__ dstv,
                                                const float* __restrict__ b1,
                                                const float* __restrict__ b2,
                                                const float* __restrict__ W3,
                                                const float* __restrict__ b3,
                                                float* __restrict__ out, int E) {
    extern __shared__ unsigned sm[];
    unsigned* Af = sm;                        // [EA_WORDS]
    unsigned* Bf = sm + EA_WORDS;             // [2][BCH_WORDS]
    float* b2s   = (float*)(Bf + 2 * BCH_WORDS);  // 256
    float* w3s   = b2s + 256;                     // 256
    float* b1s   = w3s + 256;                     // 256
    float* score = b1s + 256;                     // 128

    const int tid = threadIdx.x, lane = tid & 31, warp = tid >> 5;
    const int wm = warp >> 3, wn = warp & 7;
    const int g = lane >> 2, tg = lane & 3;
    const int e0 = blockIdx.x * 128;
    const int is64 = g_is64;

    if (tid < 256) {
        b2s[tid] = b2[tid];
        w3s[tid] = W3[tid];
        b1s[tid] = b1[tid];
    }
    if (tid < 128) score[tid] = b3[0];
    __syncthreads();

    uint4 rwv[2];
    const __half* Brow = g_W2h + (long long)(tid >> 1) * 256 + (tid & 1) * 16;
    auto LDW = [&](int kt) {
        const uint4* p = (const uint4*)(Brow + kt * 32);
        rwv[0] = p[0]; rwv[1] = p[1];
    };
    auto STW = [&](int buf) {
        const int row = tid >> 1, hB = tid & 1;
        const int Ni = row >> 3, gb = row & 7;
#pragma unroll
        for (int ii = 0; ii < 2; ii++) {
            int i = hB * 2 + ii;
            unsigned* q = Bf + buf * BCH_WORDS + (Ni * 2 + (i >> 1)) * BW + gb * 8 + (i & 1);
            q[0] = rwv[ii].x; q[2] = rwv[ii].y; q[4] = rwv[ii].z; q[6] = rwv[ii].w;
        }
    };

    LDW(0);  // overlap W2 chunk-0 loads with the gather

    // ---- gather + layer 1 (fp16 PQ, coalesced uint4, swizzled frag store) ----
    {
        const int r = tid >> 2, l4 = tid & 3;
        const int Mi = r >> 4, gg = (r & 15) & 7, hi = (r & 15) >> 3;
        const int swz = (gg >> 1) & 3;
        unsigned* fragp = Af + Mi * 16 * AW + gg * 16 + hi;
        int e = e0 + r;
        if (e >= E) e = 0;   // garbage rows computed, never stored
        long long s, d;
        if (is64) { s = ((const long long*)srcv)[e]; d = ((const long long*)dstv)[e]; }
        else      { s = ((const int*)srcv)[e];       d = ((const int*)dstv)[e]; }
        const uint4* P8 = (const uint4*)(g_PQh + s * 512);
        const uint4* Q8 = (const uint4*)(g_PQh + d * 512 + 256);
#pragma unroll
        for (int i = 0; i < 8; i++) {
            int c8 = i * 4 + l4;           // uint4 (8-half) index, 0..31
            uint4 pu = P8[c8], qu = Q8[c8];
            const float* bb = b1s + c8 * 8;
            float v[8];
            float2 a, b;
            a = h2f(pu.x); b = h2f(qu.x);
            v[0] = fmaxf(a.x + b.x + bb[0], 0.f); v[1] = fmaxf(a.y + b.y + bb[1], 0.f);
            a = h2f(pu.y); b = h2f(qu.y);
            v[2] = fmaxf(a.x + b.x + bb[2], 0.f); v[3] = fmaxf(a.y + b.y + bb[3], 0.f);
            a = h2f(pu.z); b = h2f(qu.z);
            v[4] = fmaxf(a.x + b.x + bb[4], 0.f); v[5] = fmaxf(a.y + b.y + bb[5], 0.f);
            a = h2f(pu.w); b = h2f(qu.w);
            v[6] = fmaxf(a.x + b.x + bb[6], 0.f); v[7] = fmaxf(a.y + b.y + bb[7], 0.f);
            const int Kk = c8 >> 1, hc = (c8 & 1) * 2;
            unsigned* basep = fragp + Kk * AW;
#pragma unroll
            for (int t = 0; t < 4; t++)
                basep[((t ^ swz) << 2) + hc] = f2h2(v[2 * t], v[2 * t + 1]);
        }
    }
    STW(0);
    __syncthreads();

    float acc[4][4][4];
#pragma unroll
    for (int a = 0; a < 4; a++)
#pragma unroll
        for (int b = 0; b < 4; b++)
#pragma unroll
            for (int c = 0; c < 4; c++) acc[a][b][c] = 0.f;

    const unsigned aoff = a_rd_off(lane);
    for (int kt = 0; kt < 8; ++kt) {
        const int cur = kt & 1;
        if (kt < 7) LDW(kt + 1);
        const unsigned* Bc = Bf + cur * BCH_WORDS;
#pragma unroll
        for (int h = 0; h < 2; ++h) {
            const int Kkg = kt * 2 + h;
            uint4 af[4]; uint2 bf[4];
#pragma unroll
            for (int mi = 0; mi < 4; ++mi)
                af[mi] = *(const uint4*)(Af + ((wm * 4 + mi) * 16 + Kkg) * AW + aoff);
#pragma unroll
            for (int ni = 0; ni < 4; ++ni)
                bf[ni] = *(const uint2*)(Bc + ((wn * 4 + ni) * 2 + h) * BW + lane * 2);
#pragma unroll
            for (int mi = 0; mi < 4; ++mi)
#pragma unroll
                for (int ni = 0; ni < 4; ++ni)
                    mma16(acc[mi][ni], (const unsigned*)&af[mi], (const unsigned*)&bf[ni]);
        }
        if (kt < 7) STW(cur ^ 1);
        __syncthreads();
    }

    // ---- fused layer-2 bias/relu + layer-3 dot reduction ----
#pragma unroll
    for (int mi = 0; mi < 4; ++mi) {
        float rs0 = 0.f, rs1 = 0.f;
#pragma unroll
        for (int ni = 0; ni < 4; ++ni) {
            int n = wn * 32 + ni * 8 + tg * 2;
            float w0 = w3s[n], w1 = w3s[n + 1];
            float c0 = b2s[n], c1 = b2s[n + 1];
            rs0 += fmaxf(acc[mi][ni][0] + c0, 0.f) * w0 + fmaxf(acc[mi][ni][1] + c1, 0.f) * w1;
            rs1 += fmaxf(acc[mi][ni][2] + c0, 0.f) * w0 + fmaxf(acc[mi][ni][3] + c1, 0.f) * w1;
        }
        rs0 += __shfl_xor_sync(0xffffffffu, rs0, 1);
        rs0 += __shfl_xor_sync(0xffffffffu, rs0, 2);
        rs1 += __shfl_xor_sync(0xffffffffu, rs1, 1);
        rs1 += __shfl_xor_sync(0xffffffffu, rs1, 2);
        if (tg == 0) {
            atomicAdd(&score[wm * 64 + mi * 16 + g], rs0);
            atomicAdd(&score[wm * 64 + mi * 16 + g + 8], rs1);
        }
    }
    __syncthreads();

    if (tid < 128) {
        int e = e0 + tid;
        if (e < E) out[e] = score[tid];
    }
}

// ---------------------------------------------------------------------------
// Launch
// ---------------------------------------------------------------------------
extern "C" void kernel_launch(void* const* d_in, const int* in_sizes, int n_in,
                              void* d_out, int out_size) {
    const float* x  = (const float*)d_in[0];
    const void*  sv = d_in[1];
    const void*  dv = d_in[2];
    const float* W1 = (const float*)d_in[3];
    const float* b1 = (const float*)d_in[4];
    const float* W2 = (const float*)d_in[5];
    const float* b2 = (const float*)d_in[6];
    const float* W3 = (const float*)d_in[7];
    const float* b3 = (const float*)d_in[8];
    float* out = (float*)d_out;

    const int n_nodes = in_sizes[0] / D;
    const int E       = in_sizes[1];

    const int SM_NODE = (2 * NACH_WORDS + 2 * BCH_WORDS) * 4;   // 50688 B
    const int SM_EDGE = (EA_WORDS + 2 * BCH_WORDS + 896) * 4;   // 104960 B
    cudaFuncSetAttribute(node_gemm, cudaFuncAttributeMaxDynamicSharedMemorySize, SM_NODE);
    cudaFuncSetAttribute(edge_mlp,  cudaFuncAttributeMaxDynamicSharedMemorySize, SM_EDGE);

    prep<<<193, 256>>>(W1, W2, (const int*)sv, E);

    dim3 g1((n_nodes + 127) / 128, 2);
    node_gemm<<<g1, 512, SM_NODE>>>(x, n_nodes);

    int g2 = (E + 127) / 128;
    edge_mlp<<<g2, 512, SM_EDGE>>>(sv, dv, b1, b2, W3, b3, out, E);
}